// round 9
// baseline (speedup 1.0000x reference)
#include <cuda_runtime.h>
#include <cuda_bf16.h>
#include <cstdint>

#define QT 16384
#define ST 16384
#define DD 1024
#define NL 64
#define KSLABS 32          // token slabs (512 tokens each)
#define NBLK   8           // dim blocks (128 dims each)

// ---- scratch (device globals; no allocation allowed) ----
__device__ float          g_part[KSLABS * NL * DD];   // 8 MB partial sums
__device__ float          g_counts[NL];
__device__ __nv_bfloat16  g_protobf[NL * DD];
__device__ float          g_p2[NL];

// ============================================================
// k_zero: zero counts + p2
// ============================================================
__global__ void k_zero() {
    int i = threadIdx.x;
    if (i < NL) { g_counts[i] = 0.f; g_p2[i] = 0.f; }
}

// ============================================================
// k_cnt: masked label histogram. grid 64 x 256 thr.
// ============================================================
__global__ void k_cnt(const int* __restrict__ tag, const int* __restrict__ msk) {
    __shared__ int cnt[NL];
    int t = threadIdx.x;
    if (t < NL) cnt[t] = 0;
    __syncthreads();
    int tk = blockIdx.x * 256 + t;
    if (msk[tk]) atomicAdd(&cnt[tag[tk]], 1);
    __syncthreads();
    if (t < NL && cnt[t]) atomicAdd(&g_counts[t], (float)cnt[t]);
}

// ============================================================
// k_acc2: proto partial sums as a tf32 GEMM (R5 proven form).
// grid (NBLK=8, KSLABS=32) = 256 CTAs, 256 threads (8 warps).
// ============================================================
__global__ void __launch_bounds__(256, 2) k_acc2(const float* __restrict__ emb,
                                                 const int* __restrict__ tag,
                                                 const int* __restrict__ msk) {
    __shared__ float emb_s[2][32][136];  // 34.8 KB
    __shared__ int   tag_s[2][32];       // tagm = mask? tag : -1

    int t = threadIdx.x;
    int nb = blockIdx.x;                 // dim block 0..7
    int sl = blockIdx.y;                 // token slab 0..31
    int w = t >> 5, l = t & 31;
    int g = l >> 2, tq = l & 3;
    int srow = t >> 3, sseg = t & 7;     // stager: 8 thr per token row
    int nc0 = w * 16;                    // warp dim offset within 128

    const float* ebase = emb + (size_t)(sl * 512) * DD + nb * 128;

    float acc[4][2][4];
    #pragma unroll
    for (int a = 0; a < 4; a++)
        #pragma unroll
        for (int b = 0; b < 2; b++)
            #pragma unroll
            for (int c = 0; c < 4; c++) acc[a][b][c] = 0.f;

    float4 rv[4];
    int rtag, rmsk;

    auto load_chunk = [&](int c) {
        const float* rp = ebase + (size_t)(c * 32 + srow) * DD;
        #pragma unroll
        for (int p = 0; p < 4; p++)
            rv[p] = *reinterpret_cast<const float4*>(rp + (sseg + p * 8) * 4);
        if (t < 32) {
            int tk = sl * 512 + c * 32 + t;
            rtag = __ldg(tag + tk);
            rmsk = __ldg(msk + tk);
        }
    };
    auto store_chunk = [&](int buf) {
        #pragma unroll
        for (int p = 0; p < 4; p++)
            *reinterpret_cast<float4*>(&emb_s[buf][srow][(sseg + p * 8) * 4]) = rv[p];
        if (t < 32) tag_s[buf][t] = rmsk ? rtag : -1;
    };

    load_chunk(0);
    store_chunk(0);

    for (int c = 0; c < 16; c++) {
        __syncthreads();
        if (c < 15) load_chunk(c + 1);
        int cb = c & 1;
        #pragma unroll
        for (int ks = 0; ks < 4; ks++) {
            int k0 = ks * 8;
            int t0 = tag_s[cb][k0 + tq];
            int t1 = tag_s[cb][k0 + tq + 4];
            unsigned b[2][2];
            #pragma unroll
            for (int nt = 0; nt < 2; nt++) {
                b[nt][0] = __float_as_uint(emb_s[cb][k0 + tq][nc0 + nt * 8 + g]);
                b[nt][1] = __float_as_uint(emb_s[cb][k0 + tq + 4][nc0 + nt * 8 + g]);
            }
            #pragma unroll
            for (int mt = 0; mt < 4; mt++) {
                int mlo = mt * 16 + g, mhi = mlo + 8;
                unsigned a0 = (t0 == mlo) ? 0x3F800000u : 0u;
                unsigned a1 = (t0 == mhi) ? 0x3F800000u : 0u;
                unsigned a2 = (t1 == mlo) ? 0x3F800000u : 0u;
                unsigned a3 = (t1 == mhi) ? 0x3F800000u : 0u;
                #pragma unroll
                for (int nt = 0; nt < 2; nt++)
                    asm volatile(
                        "mma.sync.aligned.m16n8k8.row.col.f32.tf32.tf32.f32 "
                        "{%0,%1,%2,%3}, {%4,%5,%6,%7}, {%8,%9}, {%0,%1,%2,%3};\n"
                        : "+f"(acc[mt][nt][0]), "+f"(acc[mt][nt][1]),
                          "+f"(acc[mt][nt][2]), "+f"(acc[mt][nt][3])
                        : "r"(a0), "r"(a1), "r"(a2), "r"(a3),
                          "r"(b[nt][0]), "r"(b[nt][1]));
            }
        }
        if (c < 15) store_chunk((c + 1) & 1);
    }

    // ---- write partial tile: g_part[sl][m][nb*128 + n] ----
    float* pb = g_part + (size_t)sl * NL * DD + nb * 128;
    #pragma unroll
    for (int mt = 0; mt < 4; mt++) {
        int mlo = mt * 16 + g, mhi = mlo + 8;
        #pragma unroll
        for (int nt = 0; nt < 2; nt++) {
            int col = nc0 + nt * 8 + 2 * tq;
            float2 lo = make_float2(acc[mt][nt][0], acc[mt][nt][1]);
            float2 hi = make_float2(acc[mt][nt][2], acc[mt][nt][3]);
            *reinterpret_cast<float2*>(pb + (size_t)mlo * DD + col) = lo;
            *reinterpret_cast<float2*>(pb + (size_t)mhi * DD + col) = hi;
        }
    }
}

// ============================================================
// k_fin2: reduce slabs, divide by counts, emit bf16 proto + p2.
// grid (64 labels, 8 dim-chunks) = 512 CTAs, 128 threads.
// ============================================================
__global__ void __launch_bounds__(128) k_fin2() {
    int n = blockIdx.x, ch = blockIdx.y, t = threadIdx.x;
    int d = ch * 128 + t;
    float s = 0.f;
    const float* pp = g_part + (size_t)n * DD + d;
    #pragma unroll
    for (int sl = 0; sl < KSLABS; sl++)
        s += pp[(size_t)sl * NL * DD];
    float v = s / fmaxf(g_counts[n], 1.f);
    g_protobf[n * DD + d] = __float2bfloat16_rn(v);
    float ps = v * v;
    #pragma unroll
    for (int o = 16; o; o >>= 1) ps += __shfl_xor_sync(0xffffffffu, ps, o);
    if ((t & 31) == 0) atomicAdd(&g_p2[n], ps);
}

// ============================================================
// k_main: 32 tokens x 64 protos, 128 threads (4 warps), grid 512.
// R5 shape (64-col chunks) + DEPTH-2 register prefetch on the
// query (DRAM) stream; proto (L2-hit) stays depth-1.
// ============================================================
__global__ void __launch_bounds__(128, 4) k_main(const float* __restrict__ q,
                                                 const int* __restrict__ qmsk,
                                                 float* __restrict__ out) {
    __shared__ __nv_bfloat16 q_sh[2][32][72];
    __shared__ __nv_bfloat16 p_sh[2][64][72];
    __shared__ float q2_sh[32], p2_sh[64];
    __shared__ int   msk_sh[32];

    int t = threadIdx.x;
    int tok0 = blockIdx.x * 32;
    if (t < 64) p2_sh[t] = g_p2[t];
    if (t >= 64 && t < 96) msk_sh[t - 64] = qmsk[tok0 + t - 64];

    int warp = t >> 5, l = t & 31;
    int wm = warp >> 1, wn = warp & 1;
    int g = l >> 2, kb = (l & 3) * 2;
    int lt = t >> 4, kv = t & 15;       // q loader: 16 thr per token row
    int prow = t >> 3, pcol = t & 7;    // proto loader

    const float* qbase = q + (size_t)tok0 * DD;

    float acc[4][4];
    #pragma unroll
    for (int b = 0; b < 4; b++)
        #pragma unroll
        for (int cc = 0; cc < 4; cc++) acc[b][cc] = 0.f;
    float q2p[4] = {0.f, 0.f, 0.f, 0.f};

    float4 vq[2][4];                    // DEPTH-2 q register staging
    uint4  pv[4];                       // depth-1 proto staging

    auto load_q = [&](int c, int rb) {
        #pragma unroll
        for (int p = 0; p < 4; p++)
            vq[rb][p] = *reinterpret_cast<const float4*>(
                qbase + (size_t)(p * 8 + lt) * DD + c * 64 + kv * 4);
    };
    auto load_p = [&](int c) {
        #pragma unroll
        for (int p = 0; p < 4; p++)
            pv[p] = *reinterpret_cast<const uint4*>(
                &g_protobf[(p * 16 + prow) * DD + c * 64 + pcol * 8]);
    };
    auto store_q = [&](int rb, int buf) {
        #pragma unroll
        for (int p = 0; p < 4; p++) {
            float4 v = vq[rb][p];
            q2p[p] += v.x * v.x + v.y * v.y + v.z * v.z + v.w * v.w;
            __nv_bfloat162 h0 = __floats2bfloat162_rn(v.x, v.y);
            __nv_bfloat162 h1 = __floats2bfloat162_rn(v.z, v.w);
            uint2 u;
            u.x = reinterpret_cast<unsigned&>(h0);
            u.y = reinterpret_cast<unsigned&>(h1);
            *reinterpret_cast<uint2*>(&q_sh[buf][p * 8 + lt][kv * 4]) = u;
        }
    };
    auto store_p = [&](int buf) {
        #pragma unroll
        for (int p = 0; p < 4; p++)
            *reinterpret_cast<uint4*>(&p_sh[buf][p * 16 + prow][pcol * 8]) = pv[p];
    };

    // prologue: chunk 0 staged to smem; chunk 1 in registers
    load_q(0, 0);
    load_p(0);
    store_q(0, 0);
    store_p(0);
    load_q(1, 1);

    for (int c = 0; c < 16; c++) {
        __syncthreads();
        if (c < 14) load_q(c + 2, c & 1);   // depth-2: window = 2 MMA blocks
        if (c < 15) load_p(c + 1);          // depth-1: L2-hit stream
        int cb = c & 1;
        #pragma unroll
        for (int s = 0; s < 4; s++) {
            int k0 = s * 16 + kb;
            unsigned a[4], b[4][2];
            {
                int r = wm * 16 + g;
                a[0] = *reinterpret_cast<const unsigned*>(&q_sh[cb][r][k0]);
                a[1] = *reinterpret_cast<const unsigned*>(&q_sh[cb][r + 8][k0]);
                a[2] = *reinterpret_cast<const unsigned*>(&q_sh[cb][r][k0 + 8]);
                a[3] = *reinterpret_cast<const unsigned*>(&q_sh[cb][r + 8][k0 + 8]);
            }
            #pragma unroll
            for (int nt = 0; nt < 4; nt++) {
                int n0 = wn * 32 + nt * 8 + g;
                b[nt][0] = *reinterpret_cast<const unsigned*>(&p_sh[cb][n0][k0]);
                b[nt][1] = *reinterpret_cast<const unsigned*>(&p_sh[cb][n0][k0 + 8]);
            }
            #pragma unroll
            for (int nt = 0; nt < 4; nt++)
                asm volatile(
                    "mma.sync.aligned.m16n8k16.row.col.f32.bf16.bf16.f32 "
                    "{%0,%1,%2,%3}, {%4,%5,%6,%7}, {%8,%9}, {%0,%1,%2,%3};\n"
                    : "+f"(acc[nt][0]), "+f"(acc[nt][1]),
                      "+f"(acc[nt][2]), "+f"(acc[nt][3])
                    : "r"(a[0]), "r"(a[1]), "r"(a[2]), "r"(a[3]),
                      "r"(b[nt][0]), "r"(b[nt][1]));
        }
        if (c < 15) {
            store_q((c + 1) & 1, (c + 1) & 1);
            store_p((c + 1) & 1);
        }
    }

    // ---- fold per-thread q2 partials (16 lanes per token row) ----
    #pragma unroll
    for (int p = 0; p < 4; p++) {
        float vv = q2p[p];
        vv += __shfl_xor_sync(0xffffffffu, vv, 8);
        vv += __shfl_xor_sync(0xffffffffu, vv, 4);
        vv += __shfl_xor_sync(0xffffffffu, vv, 2);
        vv += __shfl_xor_sync(0xffffffffu, vv, 1);
        if (kv == 0) q2_sh[p * 8 + lt] = vv;
    }
    __syncthreads();

    // ---- epilogue ----
    {
        int r0 = wm * 16 + g;
        int r1 = r0 + 8;
        float m0 = (float)msk_sh[r0], m1 = (float)msk_sh[r1];
        float q20 = q2_sh[r0], q21 = q2_sh[r1];
        #pragma unroll
        for (int nt = 0; nt < 4; nt++) {
            int cc = wn * 32 + nt * 8 + kb;
            float p20 = p2_sh[cc], p21 = p2_sh[cc + 1];
            float2 o0, o1;
            o0.x = -(q20 + p20 - 2.f * acc[nt][0]) * m0;
            o0.y = -(q20 + p21 - 2.f * acc[nt][1]) * m0;
            o1.x = -(q21 + p20 - 2.f * acc[nt][2]) * m1;
            o1.y = -(q21 + p21 - 2.f * acc[nt][3]) * m1;
            *reinterpret_cast<float2*>(out + (size_t)(tok0 + r0) * NL + cc) = o0;
            *reinterpret_cast<float2*>(out + (size_t)(tok0 + r1) * NL + cc) = o1;
        }
    }
}

// ============================================================
extern "C" void kernel_launch(void* const* d_in, const int* in_sizes, int n_in,
                              void* d_out, int out_size) {
    const float* s_emb = (const float*)d_in[0];
    const int*   s_tag = (const int*)d_in[1];
    const int*   s_msk = (const int*)d_in[2];
    const float* q_emb = (const float*)d_in[3];
    const int*   q_msk = (const int*)d_in[4];
    float* out = (float*)d_out;

    k_zero<<<1, 64>>>();
    k_cnt<<<64, 256>>>(s_tag, s_msk);
    dim3 ga(NBLK, KSLABS);
    k_acc2<<<ga, 256>>>(s_emb, s_tag, s_msk);
    dim3 gf(NL, NBLK);
    k_fin2<<<gf, 128>>>();
    k_main<<<512, 128>>>(q_emb, q_msk, out);
}

// round 10
// speedup vs baseline: 1.1190x; 1.1190x over previous
#include <cuda_runtime.h>
#include <cuda_bf16.h>
#include <cstdint>

#define QT 16384
#define ST 16384
#define DD 1024
#define NL 64
#define KSLABS 32          // token slabs (512 tokens each)
#define NBLK   8           // dim blocks (128 dims each)

// ---- scratch (device globals; no allocation allowed) ----
__device__ float          g_part[KSLABS * NL * DD];   // 8 MB partial sums
__device__ float          g_counts[NL];
__device__ __nv_bfloat16  g_protobf[NL * DD];
__device__ float          g_p2[NL];

// ============================================================
// k_zero: zero counts + p2
// ============================================================
__global__ void k_zero() {
    int i = threadIdx.x;
    if (i < NL) { g_counts[i] = 0.f; g_p2[i] = 0.f; }
}

// ============================================================
// k_cnt: masked label histogram. grid 64 x 256 thr.
// ============================================================
__global__ void k_cnt(const int* __restrict__ tag, const int* __restrict__ msk) {
    __shared__ int cnt[NL];
    int t = threadIdx.x;
    if (t < NL) cnt[t] = 0;
    __syncthreads();
    int tk = blockIdx.x * 256 + t;
    if (msk[tk]) atomicAdd(&cnt[tag[tk]], 1);
    __syncthreads();
    if (t < NL && cnt[t]) atomicAdd(&g_counts[t], (float)cnt[t]);
}

// ============================================================
// k_acc2: proto partial sums as a tf32 GEMM (R5 proven form).
// grid (NBLK=8, KSLABS=32) = 256 CTAs, 256 threads (8 warps).
// CTA tile: M=64 labels x N=128 dims, K=512 tokens, chunks of 32.
// ============================================================
__global__ void __launch_bounds__(256, 2) k_acc2(const float* __restrict__ emb,
                                                 const int* __restrict__ tag,
                                                 const int* __restrict__ msk) {
    __shared__ float emb_s[2][32][136];  // 34.8 KB
    __shared__ int   tag_s[2][32];       // tagm = mask? tag : -1

    int t = threadIdx.x;
    int nb = blockIdx.x;                 // dim block 0..7
    int sl = blockIdx.y;                 // token slab 0..31
    int w = t >> 5, l = t & 31;
    int g = l >> 2, tq = l & 3;
    int srow = t >> 3, sseg = t & 7;     // stager: 8 thr per token row
    int nc0 = w * 16;                    // warp dim offset within 128

    const float* ebase = emb + (size_t)(sl * 512) * DD + nb * 128;

    float acc[4][2][4];
    #pragma unroll
    for (int a = 0; a < 4; a++)
        #pragma unroll
        for (int b = 0; b < 2; b++)
            #pragma unroll
            for (int c = 0; c < 4; c++) acc[a][b][c] = 0.f;

    float4 rv[4];
    int rtag, rmsk;

    auto load_chunk = [&](int c) {
        const float* rp = ebase + (size_t)(c * 32 + srow) * DD;
        #pragma unroll
        for (int p = 0; p < 4; p++)
            rv[p] = *reinterpret_cast<const float4*>(rp + (sseg + p * 8) * 4);
        if (t < 32) {
            int tk = sl * 512 + c * 32 + t;
            rtag = __ldg(tag + tk);
            rmsk = __ldg(msk + tk);
        }
    };
    auto store_chunk = [&](int buf) {
        #pragma unroll
        for (int p = 0; p < 4; p++)
            *reinterpret_cast<float4*>(&emb_s[buf][srow][(sseg + p * 8) * 4]) = rv[p];
        if (t < 32) tag_s[buf][t] = rmsk ? rtag : -1;
    };

    load_chunk(0);
    store_chunk(0);

    for (int c = 0; c < 16; c++) {
        __syncthreads();
        if (c < 15) load_chunk(c + 1);
        int cb = c & 1;
        #pragma unroll
        for (int ks = 0; ks < 4; ks++) {
            int k0 = ks * 8;
            int t0 = tag_s[cb][k0 + tq];
            int t1 = tag_s[cb][k0 + tq + 4];
            unsigned b[2][2];
            #pragma unroll
            for (int nt = 0; nt < 2; nt++) {
                b[nt][0] = __float_as_uint(emb_s[cb][k0 + tq][nc0 + nt * 8 + g]);
                b[nt][1] = __float_as_uint(emb_s[cb][k0 + tq + 4][nc0 + nt * 8 + g]);
            }
            #pragma unroll
            for (int mt = 0; mt < 4; mt++) {
                int mlo = mt * 16 + g, mhi = mlo + 8;
                unsigned a0 = (t0 == mlo) ? 0x3F800000u : 0u;
                unsigned a1 = (t0 == mhi) ? 0x3F800000u : 0u;
                unsigned a2 = (t1 == mlo) ? 0x3F800000u : 0u;
                unsigned a3 = (t1 == mhi) ? 0x3F800000u : 0u;
                #pragma unroll
                for (int nt = 0; nt < 2; nt++)
                    asm volatile(
                        "mma.sync.aligned.m16n8k8.row.col.f32.tf32.tf32.f32 "
                        "{%0,%1,%2,%3}, {%4,%5,%6,%7}, {%8,%9}, {%0,%1,%2,%3};\n"
                        : "+f"(acc[mt][nt][0]), "+f"(acc[mt][nt][1]),
                          "+f"(acc[mt][nt][2]), "+f"(acc[mt][nt][3])
                        : "r"(a0), "r"(a1), "r"(a2), "r"(a3),
                          "r"(b[nt][0]), "r"(b[nt][1]));
            }
        }
        if (c < 15) store_chunk((c + 1) & 1);
    }

    // ---- write partial tile: g_part[sl][m][nb*128 + n] ----
    float* pb = g_part + (size_t)sl * NL * DD + nb * 128;
    #pragma unroll
    for (int mt = 0; mt < 4; mt++) {
        int mlo = mt * 16 + g, mhi = mlo + 8;
        #pragma unroll
        for (int nt = 0; nt < 2; nt++) {
            int col = nc0 + nt * 8 + 2 * tq;
            float2 lo = make_float2(acc[mt][nt][0], acc[mt][nt][1]);
            float2 hi = make_float2(acc[mt][nt][2], acc[mt][nt][3]);
            *reinterpret_cast<float2*>(pb + (size_t)mlo * DD + col) = lo;
            *reinterpret_cast<float2*>(pb + (size_t)mhi * DD + col) = hi;
        }
    }
}

// ============================================================
// k_fin2: reduce slabs, divide by counts, emit bf16 proto + p2.
// grid (64 labels, 8 dim-chunks) = 512 CTAs, 128 threads. (proven)
// ============================================================
__global__ void __launch_bounds__(128) k_fin2() {
    int n = blockIdx.x, ch = blockIdx.y, t = threadIdx.x;
    int d = ch * 128 + t;
    float s = 0.f;
    const float* pp = g_part + (size_t)n * DD + d;
    #pragma unroll
    for (int sl = 0; sl < KSLABS; sl++)
        s += pp[(size_t)sl * NL * DD];
    float v = s / fmaxf(g_counts[n], 1.f);
    g_protobf[n * DD + d] = __float2bfloat16_rn(v);
    float ps = v * v;
    #pragma unroll
    for (int o = 16; o; o >>= 1) ps += __shfl_xor_sync(0xffffffffu, ps, o);
    if ((t & 31) == 0) atomicAdd(&g_p2[n], ps);
}

// ============================================================
// k_main: EXACT R5 form. 32 tokens x 64 protos, 128 threads,
// 64-col chunks, depth-1 register staging, grid = 512.
// ============================================================
__global__ void __launch_bounds__(128, 5) k_main(const float* __restrict__ q,
                                                 const int* __restrict__ qmsk,
                                                 float* __restrict__ out) {
    __shared__ __nv_bfloat16 q_sh[2][32][72];
    __shared__ __nv_bfloat16 p_sh[2][64][72];
    __shared__ float q2_sh[32], p2_sh[64];
    __shared__ int   msk_sh[32];

    int t = threadIdx.x;
    int tok0 = blockIdx.x * 32;
    if (t < 64) p2_sh[t] = g_p2[t];
    if (t >= 64 && t < 96) msk_sh[t - 64] = qmsk[tok0 + t - 64];

    int warp = t >> 5, l = t & 31;
    int wm = warp >> 1, wn = warp & 1;
    int g = l >> 2, kb = (l & 3) * 2;
    int lt = t >> 4, kv = t & 15;
    int prow = t >> 3, pcol = t & 7;

    const float* qbase = q + (size_t)tok0 * DD;

    float acc[4][4];
    #pragma unroll
    for (int b = 0; b < 4; b++)
        #pragma unroll
        for (int cc = 0; cc < 4; cc++) acc[b][cc] = 0.f;
    float q2p[4] = {0.f, 0.f, 0.f, 0.f};

    float4 v[4];
    uint4  pv[4];

    auto load_chunk = [&](int c) {
        #pragma unroll
        for (int p = 0; p < 4; p++)
            v[p] = *reinterpret_cast<const float4*>(
                qbase + (size_t)(p * 8 + lt) * DD + c * 64 + kv * 4);
        #pragma unroll
        for (int p = 0; p < 4; p++)
            pv[p] = *reinterpret_cast<const uint4*>(
                &g_protobf[(p * 16 + prow) * DD + c * 64 + pcol * 8]);
    };
    auto store_chunk = [&](int buf) {
        #pragma unroll
        for (int p = 0; p < 4; p++) {
            q2p[p] += v[p].x * v[p].x + v[p].y * v[p].y
                    + v[p].z * v[p].z + v[p].w * v[p].w;
            __nv_bfloat162 h0 = __floats2bfloat162_rn(v[p].x, v[p].y);
            __nv_bfloat162 h1 = __floats2bfloat162_rn(v[p].z, v[p].w);
            uint2 u;
            u.x = reinterpret_cast<unsigned&>(h0);
            u.y = reinterpret_cast<unsigned&>(h1);
            *reinterpret_cast<uint2*>(&q_sh[buf][p * 8 + lt][kv * 4]) = u;
        }
        #pragma unroll
        for (int p = 0; p < 4; p++)
            *reinterpret_cast<uint4*>(&p_sh[buf][p * 16 + prow][pcol * 8]) = pv[p];
    };

    load_chunk(0);
    store_chunk(0);

    for (int c = 0; c < 16; c++) {
        __syncthreads();
        if (c < 15) load_chunk(c + 1);
        int cb = c & 1;
        #pragma unroll
        for (int s = 0; s < 4; s++) {
            int k0 = s * 16 + kb;
            unsigned a[4], b[4][2];
            {
                int r = wm * 16 + g;
                a[0] = *reinterpret_cast<const unsigned*>(&q_sh[cb][r][k0]);
                a[1] = *reinterpret_cast<const unsigned*>(&q_sh[cb][r + 8][k0]);
                a[2] = *reinterpret_cast<const unsigned*>(&q_sh[cb][r][k0 + 8]);
                a[3] = *reinterpret_cast<const unsigned*>(&q_sh[cb][r + 8][k0 + 8]);
            }
            #pragma unroll
            for (int nt = 0; nt < 4; nt++) {
                int n0 = wn * 32 + nt * 8 + g;
                b[nt][0] = *reinterpret_cast<const unsigned*>(&p_sh[cb][n0][k0]);
                b[nt][1] = *reinterpret_cast<const unsigned*>(&p_sh[cb][n0][k0 + 8]);
            }
            #pragma unroll
            for (int nt = 0; nt < 4; nt++)
                asm volatile(
                    "mma.sync.aligned.m16n8k16.row.col.f32.bf16.bf16.f32 "
                    "{%0,%1,%2,%3}, {%4,%5,%6,%7}, {%8,%9}, {%0,%1,%2,%3};\n"
                    : "+f"(acc[nt][0]), "+f"(acc[nt][1]),
                      "+f"(acc[nt][2]), "+f"(acc[nt][3])
                    : "r"(a[0]), "r"(a[1]), "r"(a[2]), "r"(a[3]),
                      "r"(b[nt][0]), "r"(b[nt][1]));
        }
        if (c < 15) store_chunk((c + 1) & 1);
    }

    #pragma unroll
    for (int p = 0; p < 4; p++) {
        float vv = q2p[p];
        vv += __shfl_xor_sync(0xffffffffu, vv, 8);
        vv += __shfl_xor_sync(0xffffffffu, vv, 4);
        vv += __shfl_xor_sync(0xffffffffu, vv, 2);
        vv += __shfl_xor_sync(0xffffffffu, vv, 1);
        if (kv == 0) q2_sh[p * 8 + lt] = vv;
    }
    __syncthreads();

    {
        int r0 = wm * 16 + g;
        int r1 = r0 + 8;
        float m0 = (float)msk_sh[r0], m1 = (float)msk_sh[r1];
        float q20 = q2_sh[r0], q21 = q2_sh[r1];
        #pragma unroll
        for (int nt = 0; nt < 4; nt++) {
            int cc = wn * 32 + nt * 8 + kb;
            float p20 = p2_sh[cc], p21 = p2_sh[cc + 1];
            float2 o0, o1;
            o0.x = -(q20 + p20 - 2.f * acc[nt][0]) * m0;
            o0.y = -(q20 + p21 - 2.f * acc[nt][1]) * m0;
            o1.x = -(q21 + p20 - 2.f * acc[nt][2]) * m1;
            o1.y = -(q21 + p21 - 2.f * acc[nt][3]) * m1;
            *reinterpret_cast<float2*>(out + (size_t)(tok0 + r0) * NL + cc) = o0;
            *reinterpret_cast<float2*>(out + (size_t)(tok0 + r1) * NL + cc) = o1;
        }
    }
}

// ============================================================
extern "C" void kernel_launch(void* const* d_in, const int* in_sizes, int n_in,
                              void* d_out, int out_size) {
    const float* s_emb = (const float*)d_in[0];
    const int*   s_tag = (const int*)d_in[1];
    const int*   s_msk = (const int*)d_in[2];
    const float* q_emb = (const float*)d_in[3];
    const int*   q_msk = (const int*)d_in[4];
    float* out = (float*)d_out;

    k_zero<<<1, 64>>>();
    k_cnt<<<64, 256>>>(s_tag, s_msk);
    dim3 ga(NBLK, KSLABS);
    k_acc2<<<ga, 256>>>(s_emb, s_tag, s_msk);
    dim3 gf(NL, NBLK);
    k_fin2<<<gf, 128>>>();
    k_main<<<512, 128>>>(q_emb, q_msk, out);
}

// round 11
// speedup vs baseline: 1.1794x; 1.0540x over previous
#include <cuda_runtime.h>
#include <cuda_bf16.h>
#include <cstdint>

#define QT 16384
#define ST 16384
#define DD 1024
#define NL 64
#define KSLABS 64          // token slabs (256 tokens each)
#define SLABTOK 256
#define NBLK   8           // dim blocks (128 dims each)

// ---- scratch (device globals; no allocation allowed) ----
__device__ float          g_part[KSLABS * NL * DD];     // 16 MB partial sums
__device__ float          g_cnt_part[KSLABS * NL];      // per-slab counts
__device__ __nv_bfloat16  g_protobf[NL * DD];
__device__ __align__(16) float g_p2p[NL * NBLK];        // per-chunk p2 partials

// ============================================================
// k_acc2: proto partial sums as a tf32 GEMM (R5 form, smaller
// slabs) + fused per-slab label counts (nb==0 CTAs only).
// grid (NBLK=8, KSLABS=64) = 512 CTAs, 256 threads (8 warps).
// CTA tile: M=64 labels x N=128 dims, K=256 tokens, chunks of 32.
// ============================================================
__global__ void __launch_bounds__(256, 3) k_acc2(const float* __restrict__ emb,
                                                 const int* __restrict__ tag,
                                                 const int* __restrict__ msk) {
    __shared__ float emb_s[2][32][136];  // 34.8 KB
    __shared__ int   tag_s[2][32];       // tagm = mask? tag : -1
    __shared__ int   cnt_s[NL];

    int t = threadIdx.x;
    int nb = blockIdx.x;                 // dim block 0..7
    int sl = blockIdx.y;                 // token slab 0..63
    int w = t >> 5, l = t & 31;
    int g = l >> 2, tq = l & 3;
    int srow = t >> 3, sseg = t & 7;     // stager: 8 thr per token row
    int nc0 = w * 16;                    // warp dim offset within 128

    if (nb == 0 && t < NL) cnt_s[t] = 0;

    const float* ebase = emb + (size_t)(sl * SLABTOK) * DD + nb * 128;

    float acc[4][2][4];
    #pragma unroll
    for (int a = 0; a < 4; a++)
        #pragma unroll
        for (int b = 0; b < 2; b++)
            #pragma unroll
            for (int c = 0; c < 4; c++) acc[a][b][c] = 0.f;

    float4 rv[4];
    int rtag, rmsk;

    auto load_chunk = [&](int c) {
        const float* rp = ebase + (size_t)(c * 32 + srow) * DD;
        #pragma unroll
        for (int p = 0; p < 4; p++)
            rv[p] = *reinterpret_cast<const float4*>(rp + (sseg + p * 8) * 4);
        if (t < 32) {
            int tk = sl * SLABTOK + c * 32 + t;
            rtag = __ldg(tag + tk);
            rmsk = __ldg(msk + tk);
        }
    };
    auto store_chunk = [&](int buf) {
        #pragma unroll
        for (int p = 0; p < 4; p++)
            *reinterpret_cast<float4*>(&emb_s[buf][srow][(sseg + p * 8) * 4]) = rv[p];
        if (t < 32) tag_s[buf][t] = rmsk ? rtag : -1;
    };

    load_chunk(0);
    store_chunk(0);

    for (int c = 0; c < 8; c++) {
        __syncthreads();
        if (c < 7) load_chunk(c + 1);
        int cb = c & 1;
        // fused label histogram (one warp, nb==0 CTAs), overlapped with MMAs
        if (nb == 0 && w == 0) {
            int tg = tag_s[cb][l];
            if (tg >= 0) atomicAdd(&cnt_s[tg], 1);
        }
        #pragma unroll
        for (int ks = 0; ks < 4; ks++) {
            int k0 = ks * 8;
            int t0 = tag_s[cb][k0 + tq];
            int t1 = tag_s[cb][k0 + tq + 4];
            unsigned b[2][2];
            #pragma unroll
            for (int nt = 0; nt < 2; nt++) {
                b[nt][0] = __float_as_uint(emb_s[cb][k0 + tq][nc0 + nt * 8 + g]);
                b[nt][1] = __float_as_uint(emb_s[cb][k0 + tq + 4][nc0 + nt * 8 + g]);
            }
            #pragma unroll
            for (int mt = 0; mt < 4; mt++) {
                int mlo = mt * 16 + g, mhi = mlo + 8;
                unsigned a0 = (t0 == mlo) ? 0x3F800000u : 0u;
                unsigned a1 = (t0 == mhi) ? 0x3F800000u : 0u;
                unsigned a2 = (t1 == mlo) ? 0x3F800000u : 0u;
                unsigned a3 = (t1 == mhi) ? 0x3F800000u : 0u;
                #pragma unroll
                for (int nt = 0; nt < 2; nt++)
                    asm volatile(
                        "mma.sync.aligned.m16n8k8.row.col.f32.tf32.tf32.f32 "
                        "{%0,%1,%2,%3}, {%4,%5,%6,%7}, {%8,%9}, {%0,%1,%2,%3};\n"
                        : "+f"(acc[mt][nt][0]), "+f"(acc[mt][nt][1]),
                          "+f"(acc[mt][nt][2]), "+f"(acc[mt][nt][3])
                        : "r"(a0), "r"(a1), "r"(a2), "r"(a3),
                          "r"(b[nt][0]), "r"(b[nt][1]));
            }
        }
        if (c < 7) store_chunk((c + 1) & 1);
    }

    // ---- write partial tile: g_part[sl][m][nb*128 + n] ----
    float* pb = g_part + (size_t)sl * NL * DD + nb * 128;
    #pragma unroll
    for (int mt = 0; mt < 4; mt++) {
        int mlo = mt * 16 + g, mhi = mlo + 8;
        #pragma unroll
        for (int nt = 0; nt < 2; nt++) {
            int col = nc0 + nt * 8 + 2 * tq;
            float2 lo = make_float2(acc[mt][nt][0], acc[mt][nt][1]);
            float2 hi = make_float2(acc[mt][nt][2], acc[mt][nt][3]);
            *reinterpret_cast<float2*>(pb + (size_t)mlo * DD + col) = lo;
            *reinterpret_cast<float2*>(pb + (size_t)mhi * DD + col) = hi;
        }
    }
    __syncthreads();
    if (nb == 0 && t < NL) g_cnt_part[sl * NL + t] = (float)cnt_s[t];
}

// ============================================================
// k_fin2: reduce slabs + counts, divide, emit bf16 proto + p2 partial.
// grid (64 labels, 8 dim-chunks) = 512 CTAs, 128 threads.
// ============================================================
__global__ void __launch_bounds__(128) k_fin2() {
    __shared__ float red[4];
    int n = blockIdx.x, ch = blockIdx.y, t = threadIdx.x;
    int d = ch * 128 + t;

    float s = 0.f;
    const float* pp = g_part + (size_t)n * DD + d;
    #pragma unroll
    for (int sl = 0; sl < KSLABS; sl++)
        s += pp[(size_t)sl * NL * DD];

    float cnt = 0.f;
    #pragma unroll
    for (int sl = 0; sl < KSLABS; sl++)
        cnt += g_cnt_part[sl * NL + n];

    float v = s / fmaxf(cnt, 1.f);
    g_protobf[n * DD + d] = __float2bfloat16_rn(v);

    float ps = v * v;
    #pragma unroll
    for (int o = 16; o; o >>= 1) ps += __shfl_xor_sync(0xffffffffu, ps, o);
    if ((t & 31) == 0) red[t >> 5] = ps;
    __syncthreads();
    if (t == 0) g_p2p[n * NBLK + ch] = red[0] + red[1] + red[2] + red[3];
}

// ============================================================
// k_main: EXACT R5 form (proven 21.8us). 32 tokens x 64 protos,
// 128 threads, 64-col chunks, depth-1 staging, grid = 512.
// Only change: p2 read sums the 8 per-chunk partials.
// ============================================================
__global__ void __launch_bounds__(128, 5) k_main(const float* __restrict__ q,
                                                 const int* __restrict__ qmsk,
                                                 float* __restrict__ out) {
    __shared__ __nv_bfloat16 q_sh[2][32][72];
    __shared__ __nv_bfloat16 p_sh[2][64][72];
    __shared__ float q2_sh[32], p2_sh[64];
    __shared__ int   msk_sh[32];

    int t = threadIdx.x;
    int tok0 = blockIdx.x * 32;
    if (t < 64) {
        float4 a = *reinterpret_cast<const float4*>(&g_p2p[t * 8]);
        float4 b = *reinterpret_cast<const float4*>(&g_p2p[t * 8 + 4]);
        p2_sh[t] = a.x + a.y + a.z + a.w + b.x + b.y + b.z + b.w;
    }
    if (t >= 64 && t < 96) msk_sh[t - 64] = qmsk[tok0 + t - 64];

    int warp = t >> 5, l = t & 31;
    int wm = warp >> 1, wn = warp & 1;
    int g = l >> 2, kb = (l & 3) * 2;
    int lt = t >> 4, kv = t & 15;
    int prow = t >> 3, pcol = t & 7;

    const float* qbase = q + (size_t)tok0 * DD;

    float acc[4][4];
    #pragma unroll
    for (int b = 0; b < 4; b++)
        #pragma unroll
        for (int cc = 0; cc < 4; cc++) acc[b][cc] = 0.f;
    float q2p[4] = {0.f, 0.f, 0.f, 0.f};

    float4 v[4];
    uint4  pv[4];

    auto load_chunk = [&](int c) {
        #pragma unroll
        for (int p = 0; p < 4; p++)
            v[p] = *reinterpret_cast<const float4*>(
                qbase + (size_t)(p * 8 + lt) * DD + c * 64 + kv * 4);
        #pragma unroll
        for (int p = 0; p < 4; p++)
            pv[p] = *reinterpret_cast<const uint4*>(
                &g_protobf[(p * 16 + prow) * DD + c * 64 + pcol * 8]);
    };
    auto store_chunk = [&](int buf) {
        #pragma unroll
        for (int p = 0; p < 4; p++) {
            q2p[p] += v[p].x * v[p].x + v[p].y * v[p].y
                    + v[p].z * v[p].z + v[p].w * v[p].w;
            __nv_bfloat162 h0 = __floats2bfloat162_rn(v[p].x, v[p].y);
            __nv_bfloat162 h1 = __floats2bfloat162_rn(v[p].z, v[p].w);
            uint2 u;
            u.x = reinterpret_cast<unsigned&>(h0);
            u.y = reinterpret_cast<unsigned&>(h1);
            *reinterpret_cast<uint2*>(&q_sh[buf][p * 8 + lt][kv * 4]) = u;
        }
        #pragma unroll
        for (int p = 0; p < 4; p++)
            *reinterpret_cast<uint4*>(&p_sh[buf][p * 16 + prow][pcol * 8]) = pv[p];
    };

    load_chunk(0);
    store_chunk(0);

    for (int c = 0; c < 16; c++) {
        __syncthreads();
        if (c < 15) load_chunk(c + 1);
        int cb = c & 1;
        #pragma unroll
        for (int s = 0; s < 4; s++) {
            int k0 = s * 16 + kb;
            unsigned a[4], b[4][2];
            {
                int r = wm * 16 + g;
                a[0] = *reinterpret_cast<const unsigned*>(&q_sh[cb][r][k0]);
                a[1] = *reinterpret_cast<const unsigned*>(&q_sh[cb][r + 8][k0]);
                a[2] = *reinterpret_cast<const unsigned*>(&q_sh[cb][r][k0 + 8]);
                a[3] = *reinterpret_cast<const unsigned*>(&q_sh[cb][r + 8][k0 + 8]);
            }
            #pragma unroll
            for (int nt = 0; nt < 4; nt++) {
                int n0 = wn * 32 + nt * 8 + g;
                b[nt][0] = *reinterpret_cast<const unsigned*>(&p_sh[cb][n0][k0]);
                b[nt][1] = *reinterpret_cast<const unsigned*>(&p_sh[cb][n0][k0 + 8]);
            }
            #pragma unroll
            for (int nt = 0; nt < 4; nt++)
                asm volatile(
                    "mma.sync.aligned.m16n8k16.row.col.f32.bf16.bf16.f32 "
                    "{%0,%1,%2,%3}, {%4,%5,%6,%7}, {%8,%9}, {%0,%1,%2,%3};\n"
                    : "+f"(acc[nt][0]), "+f"(acc[nt][1]),
                      "+f"(acc[nt][2]), "+f"(acc[nt][3])
                    : "r"(a[0]), "r"(a[1]), "r"(a[2]), "r"(a[3]),
                      "r"(b[nt][0]), "r"(b[nt][1]));
        }
        if (c < 15) store_chunk((c + 1) & 1);
    }

    #pragma unroll
    for (int p = 0; p < 4; p++) {
        float vv = q2p[p];
        vv += __shfl_xor_sync(0xffffffffu, vv, 8);
        vv += __shfl_xor_sync(0xffffffffu, vv, 4);
        vv += __shfl_xor_sync(0xffffffffu, vv, 2);
        vv += __shfl_xor_sync(0xffffffffu, vv, 1);
        if (kv == 0) q2_sh[p * 8 + lt] = vv;
    }
    __syncthreads();

    {
        int r0 = wm * 16 + g;
        int r1 = r0 + 8;
        float m0 = (float)msk_sh[r0], m1 = (float)msk_sh[r1];
        float q20 = q2_sh[r0], q21 = q2_sh[r1];
        #pragma unroll
        for (int nt = 0; nt < 4; nt++) {
            int cc = wn * 32 + nt * 8 + kb;
            float p20 = p2_sh[cc], p21 = p2_sh[cc + 1];
            float2 o0, o1;
            o0.x = -(q20 + p20 - 2.f * acc[nt][0]) * m0;
            o0.y = -(q20 + p21 - 2.f * acc[nt][1]) * m0;
            o1.x = -(q21 + p20 - 2.f * acc[nt][2]) * m1;
            o1.y = -(q21 + p21 - 2.f * acc[nt][3]) * m1;
            *reinterpret_cast<float2*>(out + (size_t)(tok0 + r0) * NL + cc) = o0;
            *reinterpret_cast<float2*>(out + (size_t)(tok0 + r1) * NL + cc) = o1;
        }
    }
}

// ============================================================
extern "C" void kernel_launch(void* const* d_in, const int* in_sizes, int n_in,
                              void* d_out, int out_size) {
    const float* s_emb = (const float*)d_in[0];
    const int*   s_tag = (const int*)d_in[1];
    const int*   s_msk = (const int*)d_in[2];
    const float* q_emb = (const float*)d_in[3];
    const int*   q_msk = (const int*)d_in[4];
    float* out = (float*)d_out;

    dim3 ga(NBLK, KSLABS);
    k_acc2<<<ga, 256>>>(s_emb, s_tag, s_msk);
    dim3 gf(NL, NBLK);
    k_fin2<<<gf, 128>>>();
    k_main<<<512, 128>>>(q_emb, q_msk, out);
}